// round 1
// baseline (speedup 1.0000x reference)
#include <cuda_runtime.h>
#include <math.h>

#define B  16
#define T  128
#define S  128
#define NH 64
#define DH 128
#define TS 16      // owned sites per block
#define NS 17      // computed sites (own + 1 left-halo site)
#define NQ 19      // prev-state halo sites (s0-2 .. s0+16)
#define TPB 256
#define TOUT 107   // T-1-20

// Persistent double-buffered recurrent state
__device__ float g_hn[2][B*S*NH];
__device__ float g_cn[2][B*S*NH];
__device__ float g_hs[2][B*S*NH];
__device__ float g_cs[2][B*S*NH];
__device__ float g_hd[2][B*S*DH];
__device__ float g_cd[2][B*S*DH];

// shared memory layout (in floats)
#define OFF_HNP 0
#define OFF_HSP (OFF_HNP + NQ*NH)
#define OFF_HDP (OFF_HSP + NQ*NH)
#define OFF_HNC (OFF_HDP + NQ*DH)
#define OFF_HSC (OFF_HNC + NS*NH)
#define OFF_HDC (OFF_HSC + NS*NH)
#define OFF_GN  (OFF_HDC + NS*DH)
#define OFF_GS  (OFF_GN  + NS*256)
#define OFF_GD  (OFF_GS  + NS*256)
#define OFF_XIN (OFF_GD  + NS*512)
#define OFF_O0  (OFF_XIN + NS*4)
#define OFF_O1  (OFF_O0  + NS)
#define SMEM_FLOATS (OFF_O1 + NS)

__device__ __forceinline__ float sigm(float x) { return 1.f / (1.f + __expf(-x)); }

__global__ void init_states_kernel() {
    int i = blockIdx.x * blockDim.x + threadIdx.x;
    if (i < B*S*NH) {
        g_hn[0][i] = 0.f; g_cn[0][i] = 0.f;
        g_hs[0][i] = 0.f; g_cs[0][i] = 0.f;
    }
    if (i < B*S*DH) {
        g_hd[0][i] = 0.f; g_cd[0][i] = 0.f;
    }
}

__global__ void __launch_bounds__(TPB) step_kernel(
    const float* __restrict__ xg,
    const float* __restrict__ nWx, const float* __restrict__ nWh,
    const float* __restrict__ nWa, const float* __restrict__ nWb,
    const float* __restrict__ nb,
    const float* __restrict__ sWx, const float* __restrict__ sWh,
    const float* __restrict__ sWa, const float* __restrict__ sWb,
    const float* __restrict__ sb,
    const float* __restrict__ dWx, const float* __restrict__ dWh,
    const float* __restrict__ dWa, const float* __restrict__ dWb,
    const float* __restrict__ db,
    const float* __restrict__ onW, const float* __restrict__ onb,
    const float* __restrict__ osW, const float* __restrict__ osb,
    float* __restrict__ out, int t)
{
    extern __shared__ float sm[];
    float* hnp = sm + OFF_HNP;
    float* hsp = sm + OFF_HSP;
    float* hdp = sm + OFF_HDP;
    float* hnc = sm + OFF_HNC;
    float* hsc = sm + OFF_HSC;
    float* hdc = sm + OFF_HDC;
    float* gn  = sm + OFF_GN;
    float* gs  = sm + OFF_GS;
    float* gd  = sm + OFF_GD;
    float* xin = sm + OFF_XIN;
    float* o0s = sm + OFF_O0;
    float* o1s = sm + OFF_O1;

    const int tid = threadIdx.x;
    const int bb  = blockIdx.y;
    const int s0  = blockIdx.x * TS;
    const int pp  = t & 1;
    const int qq  = pp ^ 1;

    // ---- load prev-state halos (sites s0-2 .. s0+16) ----
    for (int i = tid; i < NQ*NH; i += TPB) {
        int q = i >> 6; int sg = s0 - 2 + q;
        bool v = ((unsigned)sg < (unsigned)S);
        int gi = (bb*S + sg) * NH + (i & 63);
        hnp[i] = v ? g_hn[pp][gi] : 0.f;
        hsp[i] = v ? g_hs[pp][gi] : 0.f;
    }
    for (int i = tid; i < NQ*DH; i += TPB) {
        int q = i >> 7; int sg = s0 - 2 + q;
        bool v = ((unsigned)sg < (unsigned)S);
        hdp[i] = v ? g_hd[pp][(bb*S + sg) * DH + (i & 127)] : 0.f;
    }
    for (int i = tid; i < NS*4; i += TPB) {
        int r = i >> 2; int sg = s0 - 1 + r;
        xin[i] = ((unsigned)sg < (unsigned)S)
                 ? xg[(((size_t)bb*T + t)*S + sg)*4 + (i & 3)] : 0.f;
    }
    __syncthreads();

    // ---- n & s gates: thread tid computes gate column tid for all NS sites ----
    {
        float an[NS], asv[NS];
        float bn_ = nb[tid], bs_ = sb[tid];
        #pragma unroll
        for (int r = 0; r < NS; r++) { an[r] = bn_; asv[r] = bs_; }
        #pragma unroll
        for (int k = 0; k < 3; k++) {
            float w = nWx[k*256 + tid];
            #pragma unroll
            for (int r = 0; r < NS; r++) an[r] += xin[r*4 + k] * w;
        }
        {
            float w = sWx[tid];
            #pragma unroll
            for (int r = 0; r < NS; r++) asv[r] += xin[r*4 + 3] * w;
        }
        #pragma unroll 4
        for (int k = 0; k < NH; k++) {
            float wh = nWh[k*256 + tid], wa = nWa[k*256 + tid], wb = nWb[k*256 + tid];
            float vh = sWh[k*256 + tid], va = sWa[k*256 + tid], vb = sWb[k*256 + tid];
            #pragma unroll
            for (int q = 0; q < NQ; q++) {
                float hn_ = hnp[q*NH + k], hs_ = hsp[q*NH + k];
                // prev h at global site (s0-2+q) feeds:
                //   Wh -> site r=q-1, Wa -> site r=q-2, Wb -> site r=q
                if (q >= 1 && q <= NS) { an[q-1] += hn_*wh; asv[q-1] += hs_*vh; }
                if (q >= 2)            { an[q-2] += hn_*wa; asv[q-2] += hs_*va; }
                if (q <  NS)           { an[q]   += hn_*wb; asv[q]   += hs_*vb; }
            }
        }
        #pragma unroll
        for (int r = 0; r < NS; r++) { gn[r*256 + tid] = an[r]; gs[r*256 + tid] = asv[r]; }
    }
    __syncthreads();

    // ---- n & s cell updates ----
    for (int i = tid; i < NS*NH; i += TPB) {
        int r = i >> 6, e = i & 63;
        int sg = s0 - 1 + r;
        bool v = ((unsigned)sg < (unsigned)S);
        int gi = v ? (bb*S + sg)*NH + e : 0;
        // n cell
        {
            float ii = gn[r*256 + e],       ff = gn[r*256 + 64 + e];
            float uu = gn[r*256 + 128 + e], oo = gn[r*256 + 192 + e];
            float cp = v ? g_cn[pp][gi] : 0.f;
            float c2 = sigm(ff)*cp + sigm(ii)*tanhf(uu);
            float h  = sigm(oo)*tanhf(c2);
            if (!v) { c2 = 0.f; h = 0.f; }
            hnc[i] = h;
            if (r >= 1) { g_cn[qq][gi] = c2; g_hn[qq][gi] = h; }
        }
        // s cell
        {
            float ii = gs[r*256 + e],       ff = gs[r*256 + 64 + e];
            float uu = gs[r*256 + 128 + e], oo = gs[r*256 + 192 + e];
            float cp = v ? g_cs[pp][gi] : 0.f;
            float c2 = sigm(ff)*cp + sigm(ii)*tanhf(uu);
            float h  = sigm(oo)*tanhf(c2);
            if (!v) { c2 = 0.f; h = 0.f; }
            hsc[i] = h;
            if (r >= 1) { g_cs[qq][gi] = c2; g_hs[qq][gi] = h; }
        }
    }
    __syncthreads();

    // ---- d gates: thread tid computes gate columns tid and tid+256 ----
    {
        float a0[NS], a1[NS];
        float b0 = db[tid], b1 = db[256 + tid];
        #pragma unroll
        for (int r = 0; r < NS; r++) { a0[r] = b0; a1[r] = b1; }
        #pragma unroll 4
        for (int k = 0; k < NH; k++) {
            float w0 = dWx[k*512 + tid], w1 = dWx[k*512 + 256 + tid];
            #pragma unroll
            for (int r = 0; r < NS; r++) {
                float x = hnc[r*NH + k];
                a0[r] += x*w0; a1[r] += x*w1;
            }
        }
        #pragma unroll 4
        for (int k = 0; k < NH; k++) {
            float w0 = dWx[(NH + k)*512 + tid], w1 = dWx[(NH + k)*512 + 256 + tid];
            #pragma unroll
            for (int r = 0; r < NS; r++) {
                float x = hsc[r*NH + k];
                a0[r] += x*w0; a1[r] += x*w1;
            }
        }
        #pragma unroll 2
        for (int k = 0; k < DH; k++) {
            float wh0 = dWh[k*512 + tid], wh1 = dWh[k*512 + 256 + tid];
            float wa0 = dWa[k*512 + tid], wa1 = dWa[k*512 + 256 + tid];
            float wb0 = dWb[k*512 + tid], wb1 = dWb[k*512 + 256 + tid];
            #pragma unroll
            for (int q = 0; q < NQ; q++) {
                float h = hdp[q*DH + k];
                if (q >= 1 && q <= NS) { a0[q-1] += h*wh0; a1[q-1] += h*wh1; }
                if (q >= 2)            { a0[q-2] += h*wa0; a1[q-2] += h*wa1; }
                if (q <  NS)           { a0[q]   += h*wb0; a1[q]   += h*wb1; }
            }
        }
        #pragma unroll
        for (int r = 0; r < NS; r++) {
            gd[r*512 + tid] = a0[r];
            gd[r*512 + 256 + tid] = a1[r];
        }
    }
    __syncthreads();

    // ---- d cell update ----
    for (int i = tid; i < NS*DH; i += TPB) {
        int r = i >> 7, e = i & 127;
        int sg = s0 - 1 + r;
        bool v = ((unsigned)sg < (unsigned)S);
        int gi = v ? (bb*S + sg)*DH + e : 0;
        float ii = gd[r*512 + e],       ff = gd[r*512 + 128 + e];
        float uu = gd[r*512 + 256 + e], oo = gd[r*512 + 384 + e];
        float cp = v ? g_cd[pp][gi] : 0.f;
        float c2 = sigm(ff)*cp + sigm(ii)*tanhf(uu);
        float h  = sigm(oo)*tanhf(c2);
        if (!v) { c2 = 0.f; h = 0.f; }
        hdc[i] = h;
        if (r >= 1) { g_cd[qq][gi] = c2; g_hd[qq][gi] = h; }
    }
    __syncthreads();

    // ---- output heads: o0 = hd @ on_W + on_b ; o1 = hd @ os_W + os_b ----
    if (tid < 2*NS) {
        int r = tid % NS;
        int which = tid / NS;
        const float* W = which ? osW : onW;
        float acc = which ? osb[0] : onb[0];
        #pragma unroll 8
        for (int k = 0; k < DH; k++) acc += hdc[r*DH + k] * W[k];
        if (which) o1s[r] = acc; else o0s[r] = acc;
    }
    __syncthreads();

    // ---- assemble next-input record and write output for t >= 20 ----
    if (t >= 20 && tid >= 1 && tid <= TS) {
        int r = tid;
        int sg = s0 + r - 1;
        float o0 = o0s[r];
        float o1 = o1s[r];
        float inflow, spd;
        if (sg == 0) {
            inflow = xg[(((size_t)bb*T + (t+1))*S + 0)*4 + 1];
            spd    = xg[(((size_t)bb*T + (t+1))*S + 0)*4 + 3];
        } else {
            inflow = o0s[r-1];
            spd    = o1;
        }
        float numc = xin[r*4 + 2] + inflow - o0;
        float* o = out + ((((size_t)bb*TOUT) + (t - 20))*S + sg)*4;
        o[0] = o0; o[1] = inflow; o[2] = numc; o[3] = spd;
    }
}

extern "C" void kernel_launch(void* const* d_in, const int* in_sizes, int n_in,
                              void* d_out, int out_size) {
    const float* xg  = (const float*)d_in[0];
    const float* nWx = (const float*)d_in[1];
    const float* nWh = (const float*)d_in[2];
    const float* nWa = (const float*)d_in[3];
    const float* nWb = (const float*)d_in[4];
    const float* nb  = (const float*)d_in[5];
    const float* sWx = (const float*)d_in[6];
    const float* sWh = (const float*)d_in[7];
    const float* sWa = (const float*)d_in[8];
    const float* sWb = (const float*)d_in[9];
    const float* sb  = (const float*)d_in[10];
    const float* dWx = (const float*)d_in[11];
    const float* dWh = (const float*)d_in[12];
    const float* dWa = (const float*)d_in[13];
    const float* dWb = (const float*)d_in[14];
    const float* db  = (const float*)d_in[15];
    const float* onW = (const float*)d_in[16];
    const float* onb = (const float*)d_in[17];
    const float* osW = (const float*)d_in[18];
    const float* osb = (const float*)d_in[19];
    float* out = (float*)d_out;

    (void)in_sizes; (void)n_in; (void)out_size;

    const int smem_bytes = SMEM_FLOATS * (int)sizeof(float);
    cudaFuncSetAttribute(step_kernel,
                         cudaFuncAttributeMaxDynamicSharedMemorySize, smem_bytes);

    init_states_kernel<<<(B*S*DH + TPB - 1) / TPB, TPB>>>();

    dim3 grid(S / TS, B);
    for (int t = 0; t < T - 1; ++t) {
        step_kernel<<<grid, TPB, smem_bytes>>>(
            xg, nWx, nWh, nWa, nWb, nb,
            sWx, sWh, sWa, sWb, sb,
            dWx, dWh, dWa, dWb, db,
            onW, onb, osW, osb, out, t);
    }
}